// round 4
// baseline (speedup 1.0000x reference)
#include <cuda_runtime.h>
#include <cstdint>

#define NN 100000
#define EE 1600000
#define DD 128

// ---------------- scratch (static device globals; no runtime alloc) ----------
__device__ float g_agg[(size_t)NN * DD];
__device__ float g_h1 [(size_t)NN * DD];
__device__ float g_h2 [(size_t)NN * DD];
__device__ float g_inv[NN];
__device__ int   g_cnt[NN];
__device__ float g_wt [6][DD * DD];   // transposed weights: wt[k*D + j] = W[j*D + k]

// ---------------- small utility kernels -------------------------------------
__global__ void zero_f4_kernel(float4* p, int n4) {
    int i = blockIdx.x * blockDim.x + threadIdx.x;
    if (i < n4) p[i] = make_float4(0.f, 0.f, 0.f, 0.f);
}

__global__ void zero_i_kernel(int* p, int n) {
    int i = blockIdx.x * blockDim.x + threadIdx.x;
    if (i < n) p[i] = 0;
}

__global__ void count_kernel(const int* __restrict__ dst, int* __restrict__ cnt, int ne) {
    int e = blockIdx.x * blockDim.x + threadIdx.x;
    if (e < ne) atomicAdd(&cnt[__ldg(&dst[e])], 1);
}

__global__ void inv_kernel(const int* __restrict__ cnt, float* __restrict__ inv, int n) {
    int i = blockIdx.x * blockDim.x + threadIdx.x;
    if (i < n) {
        int c = cnt[i];
        inv[i] = 1.0f / (float)(c > 0 ? c : 1);
    }
}

// transpose all 6 weight matrices in one launch
__global__ void transpose6_kernel(const float* __restrict__ w0, const float* __restrict__ w1,
                                  const float* __restrict__ w2, const float* __restrict__ w3,
                                  const float* __restrict__ w4, const float* __restrict__ w5,
                                  float* __restrict__ wt) {
    int idx = blockIdx.x * blockDim.x + threadIdx.x;  // 0 .. 6*D*D-1
    if (idx < 6 * DD * DD) {
        int m   = idx / (DD * DD);
        int rem = idx - m * DD * DD;
        int j = rem / DD, k = rem % DD;
        const float* w = (m == 0) ? w0 : (m == 1) ? w1 : (m == 2) ? w2
                       : (m == 3) ? w3 : (m == 4) ? w4 : w5;
        wt[m * DD * DD + k * DD + j] = w[j * DD + k];
    }
}

// ---------------- scatter: agg[dst] += A[src], one warp per edge -------------
__global__ __launch_bounds__(256) void scatter_kernel(
    const float* __restrict__ A,
    const int* __restrict__ src,
    const int* __restrict__ dst,
    float* __restrict__ agg, int ne)
{
    int e = blockIdx.x * 8 + (threadIdx.x >> 5);
    if (e >= ne) return;
    int lane = threadIdx.x & 31;
    int s = __ldg(&src[e]);
    int d = __ldg(&dst[e]);
    const float4 v = *(const float4*)&A[(size_t)s * DD + lane * 4];
    float* p = &agg[(size_t)d * DD + lane * 4];
    atomicAdd(p + 0, v.x);
    atomicAdd(p + 1, v.y);
    atomicAdd(p + 2, v.z);
    atomicAdd(p + 3, v.w);
}

// ---------------- fused combine: out = act((agg*inv) @ Wl^T + A @ Wr^T + b) --
// Tile: 64 nodes x 128 cols per block, 128 threads, 8x8 micro-tile per thread.
template <bool RELU>
__global__ __launch_bounds__(128) void combine_kernel(
    const float* __restrict__ A,      // [n, 128] layer input
    const float* __restrict__ agg,    // [n, 128] summed neighbor features
    const float* __restrict__ inv,    // [n] 1/max(cnt,1)
    const float* __restrict__ Wl,     // [128,128] transposed: Wl[k*D+j]
    const float* __restrict__ Wr,     // [128,128] transposed
    const float* __restrict__ bias,   // [128]
    float* __restrict__ out, int n)
{
    __shared__ float Am[64][9];
    __shared__ float Ax[64][9];
    __shared__ __align__(16) float Wls[8][DD];
    __shared__ __align__(16) float Wrs[8][DD];

    const int t    = threadIdx.x;
    const int cg   = t & 15;    // column group: cols cg*8 .. cg*8+7
    const int ng   = t >> 4;    // node group:   nodes ng*8 .. ng*8+7
    const int node0 = blockIdx.x * 64;

    // loader mapping: thread t loads 4 floats of node (t>>1), offset (t&1)*4 within k-chunk
    const int ln = t >> 1;
    const int lp = (t & 1) * 4;
    int lnode = node0 + ln;
    if (lnode >= n) lnode = n - 1;
    const float invn = inv[lnode];

    float acc[8][8];
    #pragma unroll
    for (int a = 0; a < 8; a++)
        #pragma unroll
        for (int b = 0; b < 8; b++) acc[a][b] = 0.f;

    for (int k0 = 0; k0 < DD; k0 += 8) {
        __syncthreads();
        {
            const float4 va = *(const float4*)&agg[(size_t)lnode * DD + k0 + lp];
            const float4 vx = *(const float4*)&A  [(size_t)lnode * DD + k0 + lp];
            Am[ln][lp + 0] = va.x * invn;
            Am[ln][lp + 1] = va.y * invn;
            Am[ln][lp + 2] = va.z * invn;
            Am[ln][lp + 3] = va.w * invn;
            Ax[ln][lp + 0] = vx.x;
            Ax[ln][lp + 1] = vx.y;
            Ax[ln][lp + 2] = vx.z;
            Ax[ln][lp + 3] = vx.w;
        }
        #pragma unroll
        for (int r = 0; r < 2; r++) {
            int id = t + 128 * r;          // float4 id 0..255
            int kk = id >> 5;              // 0..7
            int j4 = (id & 31) << 2;       // 0..124
            *(float4*)&Wls[kk][j4] = *(const float4*)&Wl[(k0 + kk) * DD + j4];
            *(float4*)&Wrs[kk][j4] = *(const float4*)&Wr[(k0 + kk) * DD + j4];
        }
        __syncthreads();

        #pragma unroll
        for (int kk = 0; kk < 8; kk++) {
            float am[8], ax[8];
            #pragma unroll
            for (int ii = 0; ii < 8; ii++) {
                am[ii] = Am[ng * 8 + ii][kk];
                ax[ii] = Ax[ng * 8 + ii][kk];
            }
            const float4 wl0 = *(const float4*)&Wls[kk][cg * 8];
            const float4 wl1 = *(const float4*)&Wls[kk][cg * 8 + 4];
            const float4 wr0 = *(const float4*)&Wrs[kk][cg * 8];
            const float4 wr1 = *(const float4*)&Wrs[kk][cg * 8 + 4];
            #pragma unroll
            for (int ii = 0; ii < 8; ii++) {
                acc[ii][0] += am[ii] * wl0.x + ax[ii] * wr0.x;
                acc[ii][1] += am[ii] * wl0.y + ax[ii] * wr0.y;
                acc[ii][2] += am[ii] * wl0.z + ax[ii] * wr0.z;
                acc[ii][3] += am[ii] * wl0.w + ax[ii] * wr0.w;
                acc[ii][4] += am[ii] * wl1.x + ax[ii] * wr1.x;
                acc[ii][5] += am[ii] * wl1.y + ax[ii] * wr1.y;
                acc[ii][6] += am[ii] * wl1.z + ax[ii] * wr1.z;
                acc[ii][7] += am[ii] * wl1.w + ax[ii] * wr1.w;
            }
        }
    }

    // epilogue: bias + optional relu, guarded store
    float bj[8];
    #pragma unroll
    for (int jj = 0; jj < 8; jj++) bj[jj] = bias[cg * 8 + jj];

    #pragma unroll
    for (int ii = 0; ii < 8; ii++) {
        int node = node0 + ng * 8 + ii;
        if (node < n) {
            float v[8];
            #pragma unroll
            for (int jj = 0; jj < 8; jj++) {
                float x = acc[ii][jj] + bj[jj];
                if (RELU) x = fmaxf(x, 0.f);
                v[jj] = x;
            }
            float4* po = (float4*)&out[(size_t)node * DD + cg * 8];
            po[0] = make_float4(v[0], v[1], v[2], v[3]);
            po[1] = make_float4(v[4], v[5], v[6], v[7]);
        }
    }
}

// ---------------- host launch ------------------------------------------------
extern "C" void kernel_launch(void* const* d_in, const int* in_sizes, int n_in,
                              void* d_out, int out_size)
{
    const float* x   = (const float*)d_in[0];
    const int*   ei  = (const int*)d_in[1];     // int32! (JAX x64 disabled)
    const float* Wl1 = (const float*)d_in[2];
    const float* Wr1 = (const float*)d_in[3];
    const float* b1  = (const float*)d_in[4];
    const float* Wl2 = (const float*)d_in[5];
    const float* Wr2 = (const float*)d_in[6];
    const float* b2  = (const float*)d_in[7];
    const float* Wl3 = (const float*)d_in[8];
    const float* Wr3 = (const float*)d_in[9];
    const float* b3  = (const float*)d_in[10];
    float* out = (float*)d_out;

    const int* src = ei;
    const int* dst = ei + EE;

    // symbol addresses: resolve once, cache in statics
    static float *agg = nullptr, *h1 = nullptr, *h2 = nullptr, *inv = nullptr, *wt = nullptr;
    static int   *cnt = nullptr;
    if (!agg) {
        cudaGetSymbolAddress((void**)&agg, g_agg);
        cudaGetSymbolAddress((void**)&h1,  g_h1);
        cudaGetSymbolAddress((void**)&h2,  g_h2);
        cudaGetSymbolAddress((void**)&inv, g_inv);
        cudaGetSymbolAddress((void**)&cnt, g_cnt);
        cudaGetSymbolAddress((void**)&wt,  g_wt);
    }

    // degree counts + reciprocal (graph is the same for all 3 layers)
    zero_i_kernel<<<(NN + 255) / 256, 256>>>(cnt, NN);
    count_kernel<<<(EE + 255) / 256, 256>>>(dst, cnt, EE);
    inv_kernel<<<(NN + 255) / 256, 256>>>(cnt, inv, NN);

    // transpose all 6 weight matrices into g_wt (single launch)
    transpose6_kernel<<<(6 * DD * DD + 255) / 256, 256>>>(Wl1, Wr1, Wl2, Wr2, Wl3, Wr3, wt);

    const int n4      = NN * DD / 4;
    const int zgrid   = (n4 + 255) / 256;
    const int sgrid   = (EE + 7) / 8;
    const int cgrid   = (NN + 63) / 64;

    // ---- layer 1: x -> h1 (relu)
    zero_f4_kernel<<<zgrid, 256>>>((float4*)agg, n4);
    scatter_kernel<<<sgrid, 256>>>(x, src, dst, agg, EE);
    combine_kernel<true><<<cgrid, 128>>>(x, agg, inv,
        wt + 0 * DD * DD, wt + 1 * DD * DD, b1, h1, NN);

    // ---- layer 2: h1 -> h2 (relu)
    zero_f4_kernel<<<zgrid, 256>>>((float4*)agg, n4);
    scatter_kernel<<<sgrid, 256>>>(h1, src, dst, agg, EE);
    combine_kernel<true><<<cgrid, 128>>>(h1, agg, inv,
        wt + 2 * DD * DD, wt + 3 * DD * DD, b2, h2, NN);

    // ---- layer 3: h2 -> out (no relu)
    zero_f4_kernel<<<zgrid, 256>>>((float4*)agg, n4);
    scatter_kernel<<<sgrid, 256>>>(h2, src, dst, agg, EE);
    combine_kernel<false><<<cgrid, 128>>>(h2, agg, inv,
        wt + 4 * DD * DD, wt + 5 * DD * DD, b3, out, NN);
}

// round 5
// speedup vs baseline: 1.9425x; 1.9425x over previous
#include <cuda_runtime.h>
#include <cstdint>

#define NN 100000
#define EE 1600000
#define DD 128

// ---------------- scratch (static device globals; no runtime alloc) ----------
__device__ float g_mean[(size_t)NN * DD];
__device__ float g_h1  [(size_t)NN * DD];
__device__ float g_h2  [(size_t)NN * DD];
__device__ float g_inv [NN];
__device__ int   g_cnt [NN];
__device__ int   g_rowp[NN + 1];
__device__ int   g_curs[NN];
__device__ int   g_csrc[EE];
__device__ float g_wt  [6][DD * DD];   // transposed weights: wt[k*D + j] = W[j*D + k]

// ---- launch 0: transpose all 6 weight matrices + zero degree counters -------
__global__ void prep_kernel(const float* __restrict__ w0, const float* __restrict__ w1,
                            const float* __restrict__ w2, const float* __restrict__ w3,
                            const float* __restrict__ w4, const float* __restrict__ w5,
                            float* __restrict__ wt, int* __restrict__ cnt) {
    int idx = blockIdx.x * blockDim.x + threadIdx.x;
    if (idx < NN) cnt[idx] = 0;
    if (idx < 6 * DD * DD) {
        int m   = idx / (DD * DD);
        int rem = idx - m * DD * DD;
        int j = rem / DD, k = rem % DD;
        const float* w = (m == 0) ? w0 : (m == 1) ? w1 : (m == 2) ? w2
                       : (m == 3) ? w3 : (m == 4) ? w4 : w5;
        wt[m * DD * DD + k * DD + j] = w[j * DD + k];
    }
}

// ---- launch 1: per-destination degree histogram -----------------------------
__global__ void count_kernel(const int* __restrict__ dst, int* __restrict__ cnt, int ne) {
    int e = blockIdx.x * blockDim.x + threadIdx.x;
    if (e < ne) atomicAdd(&cnt[__ldg(&dst[e])], 1);
}

// ---- launch 2: single-block exclusive scan over 100k counts -----------------
// Also emits fill cursors and 1/max(deg,1).
__global__ __launch_bounds__(1024) void scan_kernel(
    const int* __restrict__ cnt, int* __restrict__ row_ptr,
    int* __restrict__ cursor, float* __restrict__ inv)
{
    __shared__ int part[1024];
    const int T = 1024;
    int t = threadIdx.x;
    int per = (NN + T - 1) / T;                 // 98
    int beg = t * per;
    int end = beg + per; if (end > NN) end = NN;

    int s = 0;
    for (int i = beg; i < end; i++) s += cnt[i];
    part[t] = s;
    __syncthreads();
    for (int off = 1; off < T; off <<= 1) {     // Hillis-Steele inclusive scan
        int v = (t >= off) ? part[t - off] : 0;
        __syncthreads();
        part[t] += v;
        __syncthreads();
    }
    int run = part[t] - s;                      // exclusive prefix for this chunk
    for (int i = beg; i < end; i++) {
        int c = cnt[i];
        row_ptr[i] = run;
        cursor[i]  = run;
        inv[i]     = 1.0f / (float)(c > 0 ? c : 1);
        run += c;
    }
    if (t == T - 1) row_ptr[NN] = run;
}

// ---- launch 3: bucket sources by destination --------------------------------
__global__ void fill_kernel(const int* __restrict__ src, const int* __restrict__ dst,
                            int* __restrict__ cursor, int* __restrict__ csrc, int ne) {
    int e = blockIdx.x * blockDim.x + threadIdx.x;
    if (e < ne) {
        int d = __ldg(&dst[e]);
        int pos = atomicAdd(&cursor[d], 1);
        csrc[pos] = __ldg(&src[e]);
    }
}

// ---- gather: mean[i] = inv[i] * sum_{e in row i} A[csrc[e]]  (warp/node) ----
__global__ __launch_bounds__(256) void gather_kernel(
    const float* __restrict__ A,
    const int* __restrict__ csrc,
    const int* __restrict__ row_ptr,
    const float* __restrict__ inv,
    float* __restrict__ mean)
{
    int node = blockIdx.x * 8 + (threadIdx.x >> 5);
    if (node >= NN) return;
    int lane4 = (threadIdx.x & 31) * 4;
    int beg = __ldg(&row_ptr[node]);
    int end = __ldg(&row_ptr[node + 1]);

    float ax = 0.f, ay = 0.f, az = 0.f, aw = 0.f;
    int e = beg;
    for (; e + 1 < end; e += 2) {               // 2-deep MLP
        int s0 = __ldg(&csrc[e]);
        int s1 = __ldg(&csrc[e + 1]);
        const float4 v0 = *(const float4*)&A[(size_t)s0 * DD + lane4];
        const float4 v1 = *(const float4*)&A[(size_t)s1 * DD + lane4];
        ax += v0.x + v1.x; ay += v0.y + v1.y;
        az += v0.z + v1.z; aw += v0.w + v1.w;
    }
    if (e < end) {
        int s0 = __ldg(&csrc[e]);
        const float4 v0 = *(const float4*)&A[(size_t)s0 * DD + lane4];
        ax += v0.x; ay += v0.y; az += v0.z; aw += v0.w;
    }
    float iv = __ldg(&inv[node]);
    *(float4*)&mean[(size_t)node * DD + lane4] =
        make_float4(ax * iv, ay * iv, az * iv, aw * iv);
}

// ---------------- fused combine: out = act(mean @ Wl^T + A @ Wr^T + b) -------
// Tile: 64 nodes x 128 cols per block, 128 threads, 8x8 micro-tile per thread.
template <bool RELU>
__global__ __launch_bounds__(128) void combine_kernel(
    const float* __restrict__ A,      // [n, 128] layer input
    const float* __restrict__ mean,   // [n, 128] mean-aggregated neighbors
    const float* __restrict__ Wl,     // [128,128] transposed: Wl[k*D+j]
    const float* __restrict__ Wr,     // [128,128] transposed
    const float* __restrict__ bias,   // [128]
    float* __restrict__ out, int n)
{
    __shared__ float Am[64][9];
    __shared__ float Ax[64][9];
    __shared__ __align__(16) float Wls[8][DD];
    __shared__ __align__(16) float Wrs[8][DD];

    const int t     = threadIdx.x;
    const int cg    = t & 15;    // column group: cols cg*8 .. cg*8+7
    const int ng    = t >> 4;    // node group:   nodes ng*8 .. ng*8+7
    const int node0 = blockIdx.x * 64;

    const int ln = t >> 1;
    const int lp = (t & 1) * 4;
    int lnode = node0 + ln;
    if (lnode >= n) lnode = n - 1;

    float acc[8][8];
    #pragma unroll
    for (int a = 0; a < 8; a++)
        #pragma unroll
        for (int b = 0; b < 8; b++) acc[a][b] = 0.f;

    for (int k0 = 0; k0 < DD; k0 += 8) {
        __syncthreads();
        {
            const float4 va = *(const float4*)&mean[(size_t)lnode * DD + k0 + lp];
            const float4 vx = *(const float4*)&A   [(size_t)lnode * DD + k0 + lp];
            Am[ln][lp + 0] = va.x; Am[ln][lp + 1] = va.y;
            Am[ln][lp + 2] = va.z; Am[ln][lp + 3] = va.w;
            Ax[ln][lp + 0] = vx.x; Ax[ln][lp + 1] = vx.y;
            Ax[ln][lp + 2] = vx.z; Ax[ln][lp + 3] = vx.w;
        }
        #pragma unroll
        for (int r = 0; r < 2; r++) {
            int id = t + 128 * r;          // float4 id 0..255
            int kk = id >> 5;              // 0..7
            int j4 = (id & 31) << 2;       // 0..124
            *(float4*)&Wls[kk][j4] = *(const float4*)&Wl[(k0 + kk) * DD + j4];
            *(float4*)&Wrs[kk][j4] = *(const float4*)&Wr[(k0 + kk) * DD + j4];
        }
        __syncthreads();

        #pragma unroll
        for (int kk = 0; kk < 8; kk++) {
            float am[8], ax[8];
            #pragma unroll
            for (int ii = 0; ii < 8; ii++) {
                am[ii] = Am[ng * 8 + ii][kk];
                ax[ii] = Ax[ng * 8 + ii][kk];
            }
            const float4 wl0 = *(const float4*)&Wls[kk][cg * 8];
            const float4 wl1 = *(const float4*)&Wls[kk][cg * 8 + 4];
            const float4 wr0 = *(const float4*)&Wrs[kk][cg * 8];
            const float4 wr1 = *(const float4*)&Wrs[kk][cg * 8 + 4];
            #pragma unroll
            for (int ii = 0; ii < 8; ii++) {
                acc[ii][0] += am[ii] * wl0.x + ax[ii] * wr0.x;
                acc[ii][1] += am[ii] * wl0.y + ax[ii] * wr0.y;
                acc[ii][2] += am[ii] * wl0.z + ax[ii] * wr0.z;
                acc[ii][3] += am[ii] * wl0.w + ax[ii] * wr0.w;
                acc[ii][4] += am[ii] * wl1.x + ax[ii] * wr1.x;
                acc[ii][5] += am[ii] * wl1.y + ax[ii] * wr1.y;
                acc[ii][6] += am[ii] * wl1.z + ax[ii] * wr1.z;
                acc[ii][7] += am[ii] * wl1.w + ax[ii] * wr1.w;
            }
        }
    }

    float bj[8];
    #pragma unroll
    for (int jj = 0; jj < 8; jj++) bj[jj] = bias[cg * 8 + jj];

    #pragma unroll
    for (int ii = 0; ii < 8; ii++) {
        int node = node0 + ng * 8 + ii;
        if (node < n) {
            float v[8];
            #pragma unroll
            for (int jj = 0; jj < 8; jj++) {
                float x = acc[ii][jj] + bj[jj];
                if (RELU) x = fmaxf(x, 0.f);
                v[jj] = x;
            }
            float4* po = (float4*)&out[(size_t)node * DD + cg * 8];
            po[0] = make_float4(v[0], v[1], v[2], v[3]);
            po[1] = make_float4(v[4], v[5], v[6], v[7]);
        }
    }
}

// ---------------- host launch ------------------------------------------------
extern "C" void kernel_launch(void* const* d_in, const int* in_sizes, int n_in,
                              void* d_out, int out_size)
{
    const float* x   = (const float*)d_in[0];
    const int*   ei  = (const int*)d_in[1];     // int32 (JAX x64 disabled)
    const float* Wl1 = (const float*)d_in[2];
    const float* Wr1 = (const float*)d_in[3];
    const float* b1  = (const float*)d_in[4];
    const float* Wl2 = (const float*)d_in[5];
    const float* Wr2 = (const float*)d_in[6];
    const float* b2  = (const float*)d_in[7];
    const float* Wl3 = (const float*)d_in[8];
    const float* Wr3 = (const float*)d_in[9];
    const float* b3  = (const float*)d_in[10];
    float* out = (float*)d_out;

    const int* src = ei;
    const int* dst = ei + EE;

    static float *mean = nullptr, *h1 = nullptr, *h2 = nullptr, *inv = nullptr, *wt = nullptr;
    static int   *cnt = nullptr, *rowp = nullptr, *curs = nullptr, *csrc = nullptr;
    if (!mean) {
        cudaGetSymbolAddress((void**)&mean, g_mean);
        cudaGetSymbolAddress((void**)&h1,   g_h1);
        cudaGetSymbolAddress((void**)&h2,   g_h2);
        cudaGetSymbolAddress((void**)&inv,  g_inv);
        cudaGetSymbolAddress((void**)&cnt,  g_cnt);
        cudaGetSymbolAddress((void**)&rowp, g_rowp);
        cudaGetSymbolAddress((void**)&curs, g_curs);
        cudaGetSymbolAddress((void**)&csrc, g_csrc);
        cudaGetSymbolAddress((void**)&wt,   g_wt);
    }

    const int ggrid = (NN + 7) / 8;        // gather: 8 warps/block
    const int cgrid = (NN + 63) / 64;      // combine: 64 nodes/block

    // CSR build (graph identical across layers)
    prep_kernel <<<(NN + 255) / 256, 256>>>(Wl1, Wr1, Wl2, Wr2, Wl3, Wr3, wt, cnt);  // 0
    count_kernel<<<(EE + 255) / 256, 256>>>(dst, cnt, EE);                           // 1
    scan_kernel <<<1, 1024>>>(cnt, rowp, curs, inv);                                 // 2
    fill_kernel <<<(EE + 255) / 256, 256>>>(src, dst, curs, csrc, EE);               // 3

    // ---- layer 1: x -> h1 (relu)
    gather_kernel<<<ggrid, 256>>>(x, csrc, rowp, inv, mean);                         // 4
    combine_kernel<true><<<cgrid, 128>>>(x, mean,                                    // 5 (profiled)
        wt + 0 * DD * DD, wt + 1 * DD * DD, b1, h1, NN);

    // ---- layer 2: h1 -> h2 (relu)
    gather_kernel<<<ggrid, 256>>>(h1, csrc, rowp, inv, mean);                        // 6
    combine_kernel<true><<<cgrid, 128>>>(h1, mean,
        wt + 2 * DD * DD, wt + 3 * DD * DD, b2, h2, NN);                             // 7

    // ---- layer 3: h2 -> out (no relu)
    gather_kernel<<<ggrid, 256>>>(h2, csrc, rowp, inv, mean);                        // 8
    combine_kernel<false><<<cgrid, 128>>>(h2, mean,
        wt + 4 * DD * DD, wt + 5 * DD * DD, b3, out, NN);                            // 9
}

// round 8
// speedup vs baseline: 2.1748x; 1.1196x over previous
#include <cuda_runtime.h>
#include <cstdint>

#define NN 100000
#define EE 1600000
#define DD 128

// ---------------- scratch (static device globals; no runtime alloc) ----------
__device__ float g_mean[(size_t)NN * DD];
__device__ float g_h1  [(size_t)NN * DD];
__device__ float g_h2  [(size_t)NN * DD];
__device__ float g_inv [NN];
__device__ int   g_cnt [NN];
__device__ int   g_rowp[NN + 1];
__device__ int   g_curs[NN];
__device__ int   g_csrc[EE];

// ---------------- CSR build kernels ------------------------------------------
__global__ void zero_i_kernel(int* p, int n) {
    int i = blockIdx.x * blockDim.x + threadIdx.x;
    if (i < n) p[i] = 0;
}

__global__ void count_kernel(const int* __restrict__ dst, int* __restrict__ cnt, int ne) {
    int e = blockIdx.x * blockDim.x + threadIdx.x;
    if (e < ne) atomicAdd(&cnt[__ldg(&dst[e])], 1);
}

__global__ __launch_bounds__(1024) void scan_kernel(
    const int* __restrict__ cnt, int* __restrict__ row_ptr,
    int* __restrict__ cursor, float* __restrict__ inv)
{
    __shared__ int part[1024];
    const int T = 1024;
    int t = threadIdx.x;
    int per = (NN + T - 1) / T;
    int beg = t * per;
    int end = beg + per; if (end > NN) end = NN;

    int s = 0;
    for (int i = beg; i < end; i++) s += cnt[i];
    part[t] = s;
    __syncthreads();
    for (int off = 1; off < T; off <<= 1) {
        int v = (t >= off) ? part[t - off] : 0;
        __syncthreads();
        part[t] += v;
        __syncthreads();
    }
    int run = part[t] - s;
    for (int i = beg; i < end; i++) {
        int c = cnt[i];
        row_ptr[i] = run;
        cursor[i]  = run;
        inv[i]     = 1.0f / (float)(c > 0 ? c : 1);
        run += c;
    }
    if (t == T - 1) row_ptr[NN] = run;
}

__global__ void fill_kernel(const int* __restrict__ src, const int* __restrict__ dst,
                            int* __restrict__ cursor, int* __restrict__ csrc, int ne) {
    int e = blockIdx.x * blockDim.x + threadIdx.x;
    if (e < ne) {
        int d = __ldg(&dst[e]);
        int pos = atomicAdd(&cursor[d], 1);
        csrc[pos] = __ldg(&src[e]);
    }
}

// ---------------- gather: mean[i] = inv[i] * sum A[csrc[e]] (warp/node) ------
__global__ __launch_bounds__(256) void gather_kernel(
    const float* __restrict__ A,
    const int* __restrict__ csrc,
    const int* __restrict__ row_ptr,
    const float* __restrict__ inv,
    float* __restrict__ mean)
{
    int node = blockIdx.x * 8 + (threadIdx.x >> 5);
    if (node >= NN) return;
    int lane4 = (threadIdx.x & 31) * 4;
    int beg = __ldg(&row_ptr[node]);
    int end = __ldg(&row_ptr[node + 1]);

    float ax = 0.f, ay = 0.f, az = 0.f, aw = 0.f;
    int e = beg;
    for (; e + 1 < end; e += 2) {
        int s0 = __ldg(&csrc[e]);
        int s1 = __ldg(&csrc[e + 1]);
        const float4 v0 = *(const float4*)&A[(size_t)s0 * DD + lane4];
        const float4 v1 = *(const float4*)&A[(size_t)s1 * DD + lane4];
        ax += v0.x + v1.x; ay += v0.y + v1.y;
        az += v0.z + v1.z; aw += v0.w + v1.w;
    }
    if (e < end) {
        int s0 = __ldg(&csrc[e]);
        const float4 v0 = *(const float4*)&A[(size_t)s0 * DD + lane4];
        ax += v0.x; ay += v0.y; az += v0.z; aw += v0.w;
    }
    float iv = __ldg(&inv[node]);
    *(float4*)&mean[(size_t)node * DD + lane4] =
        make_float4(ax * iv, ay * iv, az * iv, aw * iv);
}

// ---------------- tf32 mma.sync combine --------------------------------------
// C[128 nodes, 128] = [mean | A] (K=256) @ [Wl;Wr]^T + bias (, relu)
// 256 threads = 8 warps; warp (w&3) -> 32-row stripe, (w>>2) -> 64-col stripe.
// m16n8k8 tf32 fragments; K processed in 8 chunks of 32.

static __device__ __forceinline__ uint32_t f2tf32(float f) {
    uint32_t r;
    asm("cvt.rna.tf32.f32 %0, %1;" : "=r"(r) : "f"(f));
    return r;
}

static __device__ __forceinline__ void mma_tf32(
    float* d, const uint32_t* a, const uint32_t* b)
{
    asm volatile(
        "mma.sync.aligned.m16n8k8.row.col.f32.tf32.tf32.f32 "
        "{%0,%1,%2,%3}, {%4,%5,%6,%7}, {%8,%9}, {%0,%1,%2,%3};"
        : "+f"(d[0]), "+f"(d[1]), "+f"(d[2]), "+f"(d[3])
        : "r"(a[0]), "r"(a[1]), "r"(a[2]), "r"(a[3]), "r"(b[0]), "r"(b[1]));
}

#define SA 36   // smem row stride in floats (conflict-free fragment LDS)

template <bool RELU>
__global__ __launch_bounds__(256) void combine_mma_kernel(
    const float* __restrict__ A,      // [n, 128] layer input
    const float* __restrict__ mean,   // [n, 128] aggregated neighbors
    const float* __restrict__ Wl,     // [128,128] row-major
    const float* __restrict__ Wr,     // [128,128] row-major
    const float* __restrict__ bias,   // [128]
    float* __restrict__ out, int n)
{
    __shared__ uint32_t As[128 * SA];
    __shared__ uint32_t Bs[128 * SA];

    const int t    = threadIdx.x;
    const int lane = t & 31;
    const int w    = t >> 5;
    const int g    = lane >> 2;   // group id (0..7)
    const int tig  = lane & 3;    // thread in group
    const int node0 = blockIdx.x * 128;
    const int rbase = (w & 3) * 32;
    const int cbase = (w >> 2) * 64;

    float acc[2][8][4];
    #pragma unroll
    for (int mt = 0; mt < 2; mt++)
        #pragma unroll
        for (int nt = 0; nt < 8; nt++)
            #pragma unroll
            for (int q = 0; q < 4; q++) acc[mt][nt][q] = 0.f;

    for (int ch = 0; ch < 8; ch++) {
        const float* asrc = (ch < 4) ? mean : A;
        const float* bsrc = (ch < 4) ? Wl : Wr;
        const int k0 = (ch & 3) * 32;

        __syncthreads();
        // load A chunk [128 rows x 32 k] and B chunk [128 cols x 32 k] (tf32)
        #pragma unroll
        for (int it = 0; it < 4; it++) {
            int f4  = it * 256 + t;          // 0..1023
            int row = f4 >> 3;               // 0..127
            int c4  = (f4 & 7) << 2;         // 0,4,..,28
            int arow = node0 + row; if (arow >= n) arow = n - 1;
            const float4 va = *(const float4*)&asrc[(size_t)arow * DD + k0 + c4];
            const float4 vb = *(const float4*)&bsrc[row * DD + k0 + c4];
            uint32_t* pa = &As[row * SA + c4];
            pa[0] = f2tf32(va.x); pa[1] = f2tf32(va.y);
            pa[2] = f2tf32(va.z); pa[3] = f2tf32(va.w);
            uint32_t* pb = &Bs[row * SA + c4];
            pb[0] = f2tf32(vb.x); pb[1] = f2tf32(vb.y);
            pb[2] = f2tf32(vb.z); pb[3] = f2tf32(vb.w);
        }
        __syncthreads();

        #pragma unroll
        for (int ks = 0; ks < 4; ks++) {
            const int kk = ks * 8;
            uint32_t af[2][4];
            #pragma unroll
            for (int mt = 0; mt < 2; mt++) {
                int r0 = (rbase + mt * 16 + g) * SA + kk + tig;
                int r1 = (rbase + mt * 16 + 8 + g) * SA + kk + tig;
                af[mt][0] = As[r0];
                af[mt][1] = As[r1];
                af[mt][2] = As[r0 + 4];
                af[mt][3] = As[r1 + 4];
            }
            #pragma unroll
            for (int nt = 0; nt < 8; nt++) {
                uint32_t bf[2];
                int bq = (cbase + nt * 8 + g) * SA + kk + tig;
                bf[0] = Bs[bq];
                bf[1] = Bs[bq + 4];
                mma_tf32(acc[0][nt], af[0], bf);
                mma_tf32(acc[1][nt], af[1], bf);
            }
        }
    }

    // epilogue: bias + relu, c-frag cols = nt*8 + 2*tig + {0,1}
    float2 bj[8];
    #pragma unroll
    for (int nt = 0; nt < 8; nt++)
        bj[nt] = *(const float2*)&bias[cbase + nt * 8 + 2 * tig];

    #pragma unroll
    for (int mt = 0; mt < 2; mt++) {
        int r0 = node0 + rbase + mt * 16 + g;
        int r1 = r0 + 8;
        #pragma unroll
        for (int nt = 0; nt < 8; nt++) {
            int col = cbase + nt * 8 + 2 * tig;
            float v0 = acc[mt][nt][0] + bj[nt].x;
            float v1 = acc[mt][nt][1] + bj[nt].y;
            float v2 = acc[mt][nt][2] + bj[nt].x;
            float v3 = acc[mt][nt][3] + bj[nt].y;
            if (RELU) {
                v0 = fmaxf(v0, 0.f); v1 = fmaxf(v1, 0.f);
                v2 = fmaxf(v2, 0.f); v3 = fmaxf(v3, 0.f);
            }
            if (r0 < n) *(float2*)&out[(size_t)r0 * DD + col] = make_float2(v0, v1);
            if (r1 < n) *(float2*)&out[(size_t)r1 * DD + col] = make_float2(v2, v3);
        }
    }
}

// ---------------- host launch ------------------------------------------------
extern "C" void kernel_launch(void* const* d_in, const int* in_sizes, int n_in,
                              void* d_out, int out_size)
{
    const float* x   = (const float*)d_in[0];
    const int*   ei  = (const int*)d_in[1];     // int32 (JAX x64 disabled)
    const float* Wl1 = (const float*)d_in[2];
    const float* Wr1 = (const float*)d_in[3];
    const float* b1  = (const float*)d_in[4];
    const float* Wl2 = (const float*)d_in[5];
    const float* Wr2 = (const float*)d_in[6];
    const float* b2  = (const float*)d_in[7];
    const float* Wl3 = (const float*)d_in[8];
    const float* Wr3 = (const float*)d_in[9];
    const float* b3  = (const float*)d_in[10];
    float* out = (float*)d_out;

    const int* src = ei;
    const int* dst = ei + EE;

    static float *mean = nullptr, *h1 = nullptr, *h2 = nullptr, *inv = nullptr;
    static int   *cnt = nullptr, *rowp = nullptr, *curs = nullptr, *csrc = nullptr;
    if (!mean) {
        cudaGetSymbolAddress((void**)&mean, g_mean);
        cudaGetSymbolAddress((void**)&h1,   g_h1);
        cudaGetSymbolAddress((void**)&h2,   g_h2);
        cudaGetSymbolAddress((void**)&inv,  g_inv);
        cudaGetSymbolAddress((void**)&cnt,  g_cnt);
        cudaGetSymbolAddress((void**)&rowp, g_rowp);
        cudaGetSymbolAddress((void**)&curs, g_curs);
        cudaGetSymbolAddress((void**)&csrc, g_csrc);
    }

    const int ggrid = (NN + 7) / 8;
    const int cgrid = (NN + 127) / 128;

    // CSR build (graph identical across layers)
    zero_i_kernel<<<(NN + 255) / 256, 256>>>(cnt, NN);
    count_kernel <<<(EE + 255) / 256, 256>>>(dst, cnt, EE);
    scan_kernel  <<<1, 1024>>>(cnt, rowp, curs, inv);
    fill_kernel  <<<(EE + 255) / 256, 256>>>(src, dst, curs, csrc, EE);

    // ---- layer 1: x -> h1 (relu)
    gather_kernel<<<ggrid, 256>>>(x, csrc, rowp, inv, mean);
    combine_mma_kernel<true><<<cgrid, 256>>>(x, mean, Wl1, Wr1, b1, h1, NN);

    // ---- layer 2: h1 -> h2 (relu)
    gather_kernel<<<ggrid, 256>>>(h1, csrc, rowp, inv, mean);
    combine_mma_kernel<true><<<cgrid, 256>>>(h1, mean, Wl2, Wr2, b2, h2, NN);

    // ---- layer 3: h2 -> out (no relu)
    gather_kernel<<<ggrid, 256>>>(h2, csrc, rowp, inv, mean);
    combine_mma_kernel<false><<<cgrid, 256>>>(h2, mean, Wl3, Wr3, b3, out, NN);
}

// round 10
// speedup vs baseline: 2.7592x; 1.2687x over previous
#include <cuda_runtime.h>
#include <cstdint>

#define NN 100000
#define EE 1600000
#define DD 128

// ---------------- scratch (static device globals; no runtime alloc) ----------
// NOTE: device globals are zero-initialized at module load; g_cnt is re-zeroed
// by the tail kernel each call so every graph replay sees cnt == 0.
__device__ float    g_mean[(size_t)NN * DD];
__device__ float    g_h1  [(size_t)NN * DD];
__device__ float    g_h2  [(size_t)NN * DD];
__device__ float    g_inv [NN];
__device__ int      g_cnt [NN];
__device__ int      g_rowp[NN + 1];
__device__ int      g_curs[NN];
__device__ int      g_csrc[EE];
__device__ uint32_t g_wp  [3 * 32768];   // tf32 weights in fragment order, per layer

static __device__ __forceinline__ uint32_t f2tf32(float f) {
    uint32_t r;
    asm("cvt.rna.tf32.f32 %0, %1;" : "=r"(r) : "f"(f));
    return r;
}

// ---------------- CSR build kernels ------------------------------------------
__global__ void count_kernel(const int* __restrict__ dst, int* __restrict__ cnt, int ne) {
    int e = blockIdx.x * blockDim.x + threadIdx.x;
    if (e < ne) atomicAdd(&cnt[__ldg(&dst[e])], 1);
}

__global__ __launch_bounds__(1024) void scan_kernel(
    const int* __restrict__ cnt, int* __restrict__ row_ptr,
    int* __restrict__ cursor, float* __restrict__ inv)
{
    __shared__ int part[1024];
    const int T = 1024;
    int t = threadIdx.x;
    int per = (NN + T - 1) / T;
    int beg = t * per;
    int end = beg + per; if (end > NN) end = NN;

    int s = 0;
    for (int i = beg; i < end; i++) s += cnt[i];
    part[t] = s;
    __syncthreads();
    for (int off = 1; off < T; off <<= 1) {
        int v = (t >= off) ? part[t - off] : 0;
        __syncthreads();
        part[t] += v;
        __syncthreads();
    }
    int run = part[t] - s;
    for (int i = beg; i < end; i++) {
        int c = cnt[i];
        row_ptr[i] = run;
        cursor[i]  = run;
        inv[i]     = 1.0f / (float)(c > 0 ? c : 1);
        run += c;
    }
    if (t == T - 1) row_ptr[NN] = run;
}

// fill CSR + permute/convert all 6 weight matrices into tf32 fragment order.
// Fragment order (uint32 index within a layer's 32768 block):
//   idx = ((((ch*4+ks)*2+cs)*8+nt)*32+lane)*2 + r
//   j   = cs*64 + nt*8 + (lane>>2)
//   kg  = (ch&3)*32 + ks*8 + (lane&3) + 4*r ;  matrix = (ch<4) ? Wl : Wr
__global__ void fill_kernel(const int* __restrict__ src, const int* __restrict__ dst,
                            int* __restrict__ cursor, int* __restrict__ csrc, int ne,
                            const float* __restrict__ Wl1, const float* __restrict__ Wr1,
                            const float* __restrict__ Wl2, const float* __restrict__ Wr2,
                            const float* __restrict__ Wl3, const float* __restrict__ Wr3,
                            uint32_t* __restrict__ wp) {
    int e = blockIdx.x * blockDim.x + threadIdx.x;
    if (e < ne) {
        int d = __ldg(&dst[e]);
        int pos = atomicAdd(&cursor[d], 1);
        csrc[pos] = __ldg(&src[e]);
    }
    if (e < 3 * 32768) {
        int L   = e >> 15;
        int rem = e & 32767;
        int r    = rem & 1;
        int lane = (rem >> 1) & 31;
        int nt   = (rem >> 6) & 7;
        int cs   = (rem >> 9) & 1;
        int ks   = (rem >> 10) & 3;
        int ch   = (rem >> 12) & 7;
        int j  = cs * 64 + nt * 8 + (lane >> 2);
        int kg = (ch & 3) * 32 + ks * 8 + (lane & 3) + 4 * r;
        const float* wm;
        if (L == 0) wm = (ch < 4) ? Wl1 : Wr1;
        else if (L == 1) wm = (ch < 4) ? Wl2 : Wr2;
        else wm = (ch < 4) ? Wl3 : Wr3;
        wp[e] = f2tf32(wm[j * DD + kg]);
    }
}

// ---------------- gather: mean[i] = inv[i] * sum A[csrc[e]] (warp/node) ------
__global__ __launch_bounds__(256) void gather_kernel(
    const float* __restrict__ A,
    const int* __restrict__ csrc,
    const int* __restrict__ row_ptr,
    const float* __restrict__ inv,
    float* __restrict__ mean)
{
    int node = blockIdx.x * 8 + (threadIdx.x >> 5);
    if (node >= NN) return;
    int lane4 = (threadIdx.x & 31) * 4;
    int beg = __ldg(&row_ptr[node]);
    int end = __ldg(&row_ptr[node + 1]);

    float ax = 0.f, ay = 0.f, az = 0.f, aw = 0.f;
    int e = beg;
    for (; e + 3 < end; e += 4) {                 // 4-deep MLP
        int s0 = __ldg(&csrc[e]);
        int s1 = __ldg(&csrc[e + 1]);
        int s2 = __ldg(&csrc[e + 2]);
        int s3 = __ldg(&csrc[e + 3]);
        const float4 v0 = *(const float4*)&A[(size_t)s0 * DD + lane4];
        const float4 v1 = *(const float4*)&A[(size_t)s1 * DD + lane4];
        const float4 v2 = *(const float4*)&A[(size_t)s2 * DD + lane4];
        const float4 v3 = *(const float4*)&A[(size_t)s3 * DD + lane4];
        ax += (v0.x + v1.x) + (v2.x + v3.x);
        ay += (v0.y + v1.y) + (v2.y + v3.y);
        az += (v0.z + v1.z) + (v2.z + v3.z);
        aw += (v0.w + v1.w) + (v2.w + v3.w);
    }
    for (; e < end; e++) {
        int s0 = __ldg(&csrc[e]);
        const float4 v0 = *(const float4*)&A[(size_t)s0 * DD + lane4];
        ax += v0.x; ay += v0.y; az += v0.z; aw += v0.w;
    }
    float iv = __ldg(&inv[node]);
    *(float4*)&mean[(size_t)node * DD + lane4] =
        make_float4(ax * iv, ay * iv, az * iv, aw * iv);
}

// ---------------- tf32 mma.sync combine --------------------------------------
// C[128 nodes, 128] = [mean | A] (K=256) @ [Wl;Wr]^T + bias (, relu)
// B fragments stream straight from the pre-permuted tf32 table (L1/L2-hot);
// only A goes through smem (double-buffered, one sync per chunk).

static __device__ __forceinline__ void mma_tf32(
    float* d, const uint32_t* a, const uint32_t* b)
{
    asm volatile(
        "mma.sync.aligned.m16n8k8.row.col.f32.tf32.tf32.f32 "
        "{%0,%1,%2,%3}, {%4,%5,%6,%7}, {%8,%9}, {%0,%1,%2,%3};"
        : "+f"(d[0]), "+f"(d[1]), "+f"(d[2]), "+f"(d[3])
        : "r"(a[0]), "r"(a[1]), "r"(a[2]), "r"(a[3]), "r"(b[0]), "r"(b[1]));
}

#define SA 36   // smem row stride in words (conflict-free fragment LDS)

template <bool RELU>
__global__ __launch_bounds__(256) void combine_mma_kernel(
    const float* __restrict__ A,        // [n, 128] layer input
    const float* __restrict__ mean,     // [n, 128] aggregated neighbors
    const uint32_t* __restrict__ Wp,    // [32768] tf32 fragment-ordered weights
    const float* __restrict__ bias,     // [128]
    float* __restrict__ out, int n)
{
    __shared__ uint32_t As[2][128 * SA];

    const int t    = threadIdx.x;
    const int lane = t & 31;
    const int w    = t >> 5;
    const int g    = lane >> 2;
    const int tig  = lane & 3;
    const int node0 = blockIdx.x * 128;
    const int rbase = (w & 3) * 32;
    const int cs    = w >> 2;            // 0/1: 64-col stripe
    const int cbase = cs * 64;

    const uint2* wp2 = (const uint2*)Wp;  // uint2 idx = ((ch*4+ks)*2+cs)*256 + nt*32 + lane

    float acc[2][8][4];
    #pragma unroll
    for (int mt = 0; mt < 2; mt++)
        #pragma unroll
        for (int nt = 0; nt < 8; nt++)
            #pragma unroll
            for (int q = 0; q < 4; q++) acc[mt][nt][q] = 0.f;

    int lnode4 = node0 + (t >> 1);                 // fill mapping: 2 threads/row
    if (lnode4 >= n) lnode4 = n - 1;
    const int frow = t >> 1;
    const int fcol = (t & 1) * 16;                 // 16 floats per thread per row

    for (int ch = 0; ch < 8; ch++) {
        const float* asrc = (ch < 4) ? mean : A;
        const int k0 = (ch & 3) * 32;
        uint32_t* buf = As[ch & 1];
        // fill A chunk: 128 rows x 32 k, 256 threads -> each thread 16 values
        {
            const float4* rp = (const float4*)&asrc[(size_t)lnode4 * DD + k0 + fcol];
            uint32_t* pa = &buf[frow * SA + fcol];
            #pragma unroll
            for (int q = 0; q < 4; q++) {
                float4 v = rp[q];
                pa[q * 4 + 0] = f2tf32(v.x);
                pa[q * 4 + 1] = f2tf32(v.y);
                pa[q * 4 + 2] = f2tf32(v.z);
                pa[q * 4 + 3] = f2tf32(v.w);
            }
        }
        __syncthreads();

        #pragma unroll
        for (int ks = 0; ks < 4; ks++) {
            const int kk = ks * 8;
            uint32_t af[2][4];
            #pragma unroll
            for (int mt = 0; mt < 2; mt++) {
                int r0 = (rbase + mt * 16 + g) * SA + kk + tig;
                int r1 = (rbase + mt * 16 + 8 + g) * SA + kk + tig;
                af[mt][0] = buf[r0];
                af[mt][1] = buf[r1];
                af[mt][2] = buf[r0 + 4];
                af[mt][3] = buf[r1 + 4];
            }
            uint2 bf[8];
            const uint2* wq = wp2 + ((ch * 4 + ks) * 2 + cs) * 256 + lane;
            #pragma unroll
            for (int nt = 0; nt < 8; nt++) bf[nt] = __ldg(wq + nt * 32);
            #pragma unroll
            for (int nt = 0; nt < 8; nt++) {
                mma_tf32(acc[0][nt], af[0], (const uint32_t*)&bf[nt]);
                mma_tf32(acc[1][nt], af[1], (const uint32_t*)&bf[nt]);
            }
        }
    }

    // epilogue: bias + relu; c-frag cols = cbase + nt*8 + 2*tig + {0,1}
    #pragma unroll
    for (int mt = 0; mt < 2; mt++) {
        int r0 = node0 + rbase + mt * 16 + g;
        int r1 = r0 + 8;
        #pragma unroll
        for (int nt = 0; nt < 8; nt++) {
            int col = cbase + nt * 8 + 2 * tig;
            float2 bj = *(const float2*)&bias[col];
            float v0 = acc[mt][nt][0] + bj.x;
            float v1 = acc[mt][nt][1] + bj.y;
            float v2 = acc[mt][nt][2] + bj.x;
            float v3 = acc[mt][nt][3] + bj.y;
            if (RELU) {
                v0 = fmaxf(v0, 0.f); v1 = fmaxf(v1, 0.f);
                v2 = fmaxf(v2, 0.f); v3 = fmaxf(v3, 0.f);
            }
            if (r0 < n) *(float2*)&out[(size_t)r0 * DD + col] = make_float2(v0, v1);
            if (r1 < n) *(float2*)&out[(size_t)r1 * DD + col] = make_float2(v2, v3);
        }
    }
}

// ---------------- tail: restore cnt == 0 for the next graph replay -----------
__global__ void tail_zero_kernel(int* p, int n) {
    int i = blockIdx.x * blockDim.x + threadIdx.x;
    if (i < n) p[i] = 0;
}

// ---------------- host launch ------------------------------------------------
extern "C" void kernel_launch(void* const* d_in, const int* in_sizes, int n_in,
                              void* d_out, int out_size)
{
    const float* x   = (const float*)d_in[0];
    const int*   ei  = (const int*)d_in[1];     // int32 (JAX x64 disabled)
    const float* Wl1 = (const float*)d_in[2];
    const float* Wr1 = (const float*)d_in[3];
    const float* b1  = (const float*)d_in[4];
    const float* Wl2 = (const float*)d_in[5];
    const float* Wr2 = (const float*)d_in[6];
    const float* b2  = (const float*)d_in[7];
    const float* Wl3 = (const float*)d_in[8];
    const float* Wr3 = (const float*)d_in[9];
    const float* b3  = (const float*)d_in[10];
    float* out = (float*)d_out;

    const int* src = ei;
    const int* dst = ei + EE;

    static float    *mean = nullptr, *h1 = nullptr, *h2 = nullptr, *inv = nullptr;
    static int      *cnt = nullptr, *rowp = nullptr, *curs = nullptr, *csrc = nullptr;
    static uint32_t *wp = nullptr;
    if (!mean) {
        cudaGetSymbolAddress((void**)&mean, g_mean);
        cudaGetSymbolAddress((void**)&h1,   g_h1);
        cudaGetSymbolAddress((void**)&h2,   g_h2);
        cudaGetSymbolAddress((void**)&inv,  g_inv);
        cudaGetSymbolAddress((void**)&cnt,  g_cnt);
        cudaGetSymbolAddress((void**)&rowp, g_rowp);
        cudaGetSymbolAddress((void**)&curs, g_curs);
        cudaGetSymbolAddress((void**)&csrc, g_csrc);
        cudaGetSymbolAddress((void**)&wp,   g_wp);
    }

    const int ggrid = (NN + 7) / 8;
    const int cgrid = (NN + 127) / 128;

    // CSR build + weight permute (cnt is 0: module-load init / tail re-zero)
    count_kernel <<<(EE + 255) / 256, 256>>>(dst, cnt, EE);                     // 0
    scan_kernel  <<<1, 1024>>>(cnt, rowp, curs, inv);                           // 1
    fill_kernel  <<<(EE + 255) / 256, 256>>>(src, dst, curs, csrc, EE,          // 2
                                             Wl1, Wr1, Wl2, Wr2, Wl3, Wr3, wp);

    // ---- layer 1: x -> h1 (relu)
    gather_kernel<<<ggrid, 256>>>(x, csrc, rowp, inv, mean);                    // 3 (profiled)
    combine_mma_kernel<true><<<cgrid, 256>>>(x, mean, wp, b1, h1, NN);          // 4

    // ---- layer 2: h1 -> h2 (relu)
    gather_kernel<<<ggrid, 256>>>(h1, csrc, rowp, inv, mean);                   // 5
    combine_mma_kernel<true><<<cgrid, 256>>>(h1, mean, wp + 32768, b2, h2, NN); // 6

    // ---- layer 3: h2 -> out (no relu)
    gather_kernel<<<ggrid, 256>>>(h2, csrc, rowp, inv, mean);                   // 7
    combine_mma_kernel<false><<<cgrid, 256>>>(h2, mean, wp + 65536, b3, out, NN); // 8

    // restore cnt for next replay
    tail_zero_kernel<<<(NN + 255) / 256, 256>>>(cnt, NN);                       // 9
}